// round 12
// baseline (speedup 1.0000x reference)
#include <cuda_runtime.h>
#include <cuda_bf16.h>
#include <cstdint>

#define BATCH 1024
#define NCEN  100000
#define NPAD  100096          // 782 * 128
#define NTILES 782
#define DIM   128
#define KNN   200
#define NCLS  100
#define GC    0.005f

#define NSAMP 6144            // sample centres (48 n-tiles)
#define TSAMP 60              // sample rank for threshold
#define CAP   3072            // candidate list capacity per query
#define KEEP  240             // approx-rank keep target
#define KMAX  512             // kept-candidate buffer
#define NBINS 4096
#define CHUNK 2               // n-tiles per CTA (main GEMM)

// ---------------- device scratch -------------------------------------------
__device__ __nv_bfloat16 g_Ahi[BATCH * DIM];
__device__ __nv_bfloat16 g_Bhi[(size_t)NPAD * DIM];
__device__ float g_fnorm[BATCH];
__device__ float g_cnorm[NCEN];
__device__ float g_D2s[(size_t)BATCH * NSAMP];
__device__ float g_edge[BATCH];
__device__ unsigned int g_cnt[BATCH];
__device__ float g_cd2[(size_t)BATCH * CAP];
__device__ int   g_cidx[(size_t)BATCH * CAP];

// ---------------- helpers ---------------------------------------------------
__device__ __forceinline__ uint32_t smem_u32(const void* p) {
    uint32_t a;
    asm("{ .reg .u64 t; cvta.to.shared.u64 t, %1; cvt.u32.u64 %0, t; }"
        : "=r"(a) : "l"(p));
    return a;
}
__device__ __forceinline__ void ldsm4(uint32_t* r, uint32_t addr) {
    asm volatile("ldmatrix.sync.aligned.m8n8.x4.shared.b16 {%0,%1,%2,%3}, [%4];"
                 : "=r"(r[0]), "=r"(r[1]), "=r"(r[2]), "=r"(r[3]) : "r"(addr));
}
__device__ __forceinline__ void mma16816(float* d, const uint32_t* a,
                                         const uint32_t* b) {
    asm volatile(
        "mma.sync.aligned.m16n8k16.row.col.f32.bf16.bf16.f32 "
        "{%0,%1,%2,%3}, {%4,%5,%6,%7}, {%8,%9}, {%0,%1,%2,%3};"
        : "+f"(d[0]), "+f"(d[1]), "+f"(d[2]), "+f"(d[3])
        : "r"(a[0]), "r"(a[1]), "r"(a[2]), "r"(a[3]), "r"(b[0]), "r"(b[1]));
}
__device__ __forceinline__ void cp16(uint32_t dst, const void* src) {
    asm volatile("cp.async.cg.shared.global [%0], [%1], 16;"
                 :: "r"(dst), "l"(src) : "memory");
}
__device__ __forceinline__ int bucket_of(float v) {
    unsigned int u = __float_as_uint(v);
    if ((int)u <= 0) return 0;
    int b = (int)(u >> 15) - 32512;
    return b < 0 ? 0 : (b > NBINS - 1 ? NBINS - 1 : b);
}
// block-wide (256 threads): smallest bucket T with cum(hist[0..T]) >= rank
__device__ int bucket_rank(unsigned int* hist, unsigned int* scanbuf,
                           int* sres, int rank, int tid) {
    unsigned int ls = 0;
    int base = tid * (NBINS / 256);
    #pragma unroll
    for (int j = 0; j < NBINS / 256; j++) ls += hist[base + j];
    scanbuf[tid] = ls;
    __syncthreads();
    for (int off = 1; off < 256; off <<= 1) {
        unsigned int v = (tid >= off) ? scanbuf[tid - off] : 0u;
        __syncthreads();
        scanbuf[tid] += v;
        __syncthreads();
    }
    unsigned int incl = scanbuf[tid], excl = incl - ls;
    if (excl < (unsigned)rank && incl >= (unsigned)rank) {
        unsigned int c = excl;
        for (int j = 0; j < NBINS / 256; j++) {
            c += hist[base + j];
            if (c >= (unsigned)rank) { *sres = base + j; break; }
        }
    }
    __syncthreads();
    return *sres;
}

// ---------------- prep: norms + hi bf16 (+ zero g_cnt) -----------------------
__global__ void prep_kernel(const float* __restrict__ in, int which) {
    if (!which) {
        int z = blockIdx.x * 8 + (threadIdx.x & 7);
        if (threadIdx.x < 8) g_cnt[z] = 0u;
    }
    int w = blockIdx.x * 8 + (threadIdx.x >> 5);
    int lane = threadIdx.x & 31;
    if (w >= (which ? NPAD : BATCH)) return;
    __nv_bfloat16* hi = which ? g_Bhi : g_Ahi;
    float4 v = make_float4(0.f, 0.f, 0.f, 0.f);
    if (!which || w < NCEN) v = ((const float4*)(in + (size_t)w * DIM))[lane];
    float s = v.x * v.x + v.y * v.y + v.z * v.z + v.w * v.w;
    #pragma unroll
    for (int o = 16; o; o >>= 1) s += __shfl_xor_sync(0xFFFFFFFFu, s, o);
    if (!lane) {
        if (which) { if (w < NCEN) g_cnorm[w] = s; }
        else g_fnorm[w] = s;
    }
    float f[4] = { v.x, v.y, v.z, v.w };
    ushort4 ph;
    unsigned short* hp = &ph.x;
    #pragma unroll
    for (int i = 0; i < 4; i++) {
        __nv_bfloat16 h = __float2bfloat16(f[i]);
        hp[i] = *(unsigned short*)&h;
    }
    ((ushort4*)(hi + (size_t)w * DIM))[lane] = ph;
}

// ---------------- GEMM bodies ------------------------------------------------
// smem: A @ 0 (32 KB), B buf0 @ 32768, B buf1 @ 65536. Total 96 KB.
#define SMT 98304
__device__ __forceinline__ uint32_t swoff(int row, int chunk) {
    return (uint32_t)(row * 256 + ((chunk ^ (row & 7)) << 4));
}
__device__ __forceinline__ void push_cand(int m, float v, int n) {
    unsigned int p = atomicAdd(&g_cnt[m], 1u);
    if (p < CAP) {
        g_cd2[(size_t)m * CAP + p] = v;
        g_cidx[(size_t)m * CAP + p] = n;
    }
}

struct WarpGeom {
    int wm, wn, rowA, cgA, sxA, rowB, cgB, sxB, qrow, qcol;
};
__device__ __forceinline__ WarpGeom geom(int tid) {
    WarpGeom w;
    int lane = tid & 31, wid = tid >> 5;
    w.wm = (wid & 3) * 32;
    w.wn = (wid >> 2) * 32;
    int g = lane >> 3, l7 = lane & 7;
    w.rowA = w.wm + ((g & 1) << 3) + l7;
    w.cgA  = g >> 1;
    w.sxA  = w.rowA & 7;
    w.rowB = w.wn + ((g >> 1) << 3) + l7;
    w.cgB  = g & 1;
    w.sxB  = w.rowB & 7;
    w.qrow = lane >> 2;
    w.qcol = (lane & 3) << 1;
    return w;
}

__device__ __forceinline__ void load_frags(uint32_t sb, uint32_t bbase,
                                           const WarpGeom& w, int ks,
                                           uint32_t afr[2][4],
                                           uint32_t bfr[2][4]) {
    int c0 = ks * 2;
    #pragma unroll
    for (int mt = 0; mt < 2; mt++)
        ldsm4(afr[mt], sb + (uint32_t)((w.rowA + mt * 16) * 256
                             + (((c0 + w.cgA) ^ w.sxA) << 4)));
    #pragma unroll
    for (int ng = 0; ng < 2; ng++)
        ldsm4(bfr[ng], bbase + (uint32_t)((w.rowB + ng * 16) * 256
                             + (((c0 + w.cgB) ^ w.sxB) << 4)));
}

// software-pipelined: frags for ks+1 load while ks's MMAs issue
__device__ __forceinline__ void compute_tile(uint32_t sb, uint32_t bbase,
                                             const WarpGeom& w,
                                             float acc[2][4][4]) {
    #pragma unroll
    for (int mt = 0; mt < 2; mt++)
        #pragma unroll
        for (int nt = 0; nt < 4; nt++)
            #pragma unroll
            for (int r = 0; r < 4; r++) acc[mt][nt][r] = 0.f;

    uint32_t afr[2][2][4], bfr[2][2][4];
    load_frags(sb, bbase, w, 0, afr[0], bfr[0]);
    #pragma unroll
    for (int ks = 0; ks < 8; ks++) {
        int cur = ks & 1;
        if (ks < 7)
            load_frags(sb, bbase, w, ks + 1, afr[cur ^ 1], bfr[cur ^ 1]);
        #pragma unroll
        for (int mt = 0; mt < 2; mt++)
            #pragma unroll
            for (int nt = 0; nt < 4; nt++)
                mma16816(acc[mt][nt], afr[cur][mt],
                         &bfr[cur][nt >> 1][(nt & 1) * 2]);
    }
}

// sample GEMM: one tile per CTA, store approx d2 rows
__global__ __launch_bounds__(512)
void sample_mma_kernel() {
    extern __shared__ char smem[];
    uint32_t sb = smem_u32(smem);
    const int tid = threadIdx.x;
    const int bm = blockIdx.x * 128;
    const int bn = blockIdx.y * 128;
    WarpGeom w = geom(tid);

    #pragma unroll
    for (int it = 0; it < 4; it++) {
        int q = it * 512 + tid;
        int row = q >> 4, chunk = q & 15;
        cp16(sb + swoff(row, chunk),
             g_Ahi + (size_t)(bm + row) * DIM + (chunk << 3));
        cp16(sb + 32768u + swoff(row, chunk),
             g_Bhi + (size_t)(bn + row) * DIM + (chunk << 3));
    }
    asm volatile("cp.async.commit_group;" ::: "memory");
    asm volatile("cp.async.wait_group 0;" ::: "memory");
    __syncthreads();

    float acc[2][4][4];
    compute_tile(sb, sb + 32768u, w, acc);

    #pragma unroll
    for (int mt = 0; mt < 2; mt++) {
        int m0 = bm + w.wm + mt * 16 + w.qrow;
        float fn0 = g_fnorm[m0], fn1 = g_fnorm[m0 + 8];
        #pragma unroll
        for (int nt = 0; nt < 4; nt++) {
            int n = bn + w.wn + nt * 8 + w.qcol;
            float2 cn = *(const float2*)(g_cnorm + n);
            *(float2*)(g_D2s + (size_t)m0 * NSAMP + n) =
                make_float2(fn0 + cn.x - 2.f * acc[mt][nt][0],
                            fn0 + cn.y - 2.f * acc[mt][nt][1]);
            *(float2*)(g_D2s + (size_t)(m0 + 8) * NSAMP + n) =
                make_float2(fn1 + cn.x - 2.f * acc[mt][nt][2],
                            fn1 + cn.y - 2.f * acc[mt][nt][3]);
        }
    }
}

// main GEMM: CHUNK tiles per CTA, filter epilogue, B double-buffered
__global__ __launch_bounds__(512)
void dist_mma_kernel() {
    extern __shared__ char smem[];
    uint32_t sb = smem_u32(smem);
    const int tid = threadIdx.x;
    const int bm = blockIdx.x * 128;   // m fastest: m-CTAs share B via L2
    const int t0 = blockIdx.y * CHUNK;
    WarpGeom w = geom(tid);

    #pragma unroll
    for (int it = 0; it < 4; it++) {
        int q = it * 512 + tid;
        int row = q >> 4, chunk = q & 15;
        cp16(sb + swoff(row, chunk),
             g_Ahi + (size_t)(bm + row) * DIM + (chunk << 3));
        cp16(sb + 32768u + swoff(row, chunk),
             g_Bhi + (size_t)(t0 * 128 + row) * DIM + (chunk << 3));
    }
    asm volatile("cp.async.commit_group;" ::: "memory");
    #pragma unroll
    for (int it = 0; it < 4; it++) {
        int q = it * 512 + tid;
        int row = q >> 4, chunk = q & 15;
        cp16(sb + 65536u + swoff(row, chunk),
             g_Bhi + (size_t)((t0 + 1) * 128 + row) * DIM + (chunk << 3));
    }
    asm volatile("cp.async.commit_group;" ::: "memory");

    // per-thread row constants hoisted out of the tile loop
    float fnv[2][2], edv[2][2];
    #pragma unroll
    for (int mt = 0; mt < 2; mt++) {
        int m0 = bm + w.wm + mt * 16 + w.qrow;
        fnv[mt][0] = g_fnorm[m0];     fnv[mt][1] = g_fnorm[m0 + 8];
        edv[mt][0] = g_edge[m0];      edv[mt][1] = g_edge[m0 + 8];
    }

    #pragma unroll
    for (int ti = 0; ti < CHUNK; ti++) {
        if (ti == 0)
            asm volatile("cp.async.wait_group 1;" ::: "memory");
        else
            asm volatile("cp.async.wait_group 0;" ::: "memory");
        __syncthreads();   // make this tile's staged B visible to all warps

        float acc[2][4][4];
        compute_tile(sb, sb + 32768u + (uint32_t)(ti * 32768), w, acc);

        int bn = (t0 + ti) * 128;
        #pragma unroll
        for (int mt = 0; mt < 2; mt++) {
            int m0 = bm + w.wm + mt * 16 + w.qrow;
            float fn0 = fnv[mt][0], fn1 = fnv[mt][1];
            float e0 = edv[mt][0],  e1 = edv[mt][1];
            #pragma unroll
            for (int nt = 0; nt < 4; nt++) {
                int n = bn + w.wn + nt * 8 + w.qcol;   // even => n+1 valid too
                if (n >= NCEN) continue;
                float2 cn = *(const float2*)(g_cnorm + n);
                float v0 = fn0 + cn.x - 2.f * acc[mt][nt][0];
                float v1 = fn0 + cn.y - 2.f * acc[mt][nt][1];
                float v2 = fn1 + cn.x - 2.f * acc[mt][nt][2];
                float v3 = fn1 + cn.y - 2.f * acc[mt][nt][3];
                if (v0 < e0) push_cand(m0, v0, n);
                if (v1 < e0) push_cand(m0, v1, n + 1);
                if (v2 < e1) push_cand(m0 + 8, v2, n);
                if (v3 < e1) push_cand(m0 + 8, v3, n + 1);
            }
        }
        // no trailing sync: B0/B1 are distinct buffers, never overwritten
    }
}

// ---------------- threshold kernel ------------------------------------------
__global__ __launch_bounds__(256)
void thresh_kernel() {
    __shared__ unsigned int hist[NBINS];
    __shared__ unsigned int scanbuf[256];
    __shared__ int sres;
    int b = blockIdx.x, tid = threadIdx.x;
    for (int i = tid; i < NBINS; i += 256) hist[i] = 0u;
    __syncthreads();
    const float* row = g_D2s + (size_t)b * NSAMP;
    for (int s = tid; s < NSAMP; s += 256)
        atomicAdd(&hist[bucket_of(row[s])], 1u);
    __syncthreads();
    int T = bucket_rank(hist, scanbuf, &sres, TSAMP, tid);
    if (tid == 0)
        g_edge[b] = __uint_as_float((unsigned int)(T + 32513) << 15);
}

// ---------------- selection: candidates -> exact top-200 -> logprobs --------
__global__ __launch_bounds__(256)
void select_kernel(const float* __restrict__ features,
                   const float* __restrict__ centres,
                   const float* __restrict__ wgt,
                   const int*   __restrict__ lab32,
                   float*       __restrict__ out) {
    __shared__ float        scd2[CAP];
    __shared__ int          scidx[CAP];
    __shared__ unsigned int hist[NBINS];
    __shared__ float        kd2[KMAX];
    __shared__ int          kidx[KMAX];
    __shared__ float        fvec[DIM];
    __shared__ float        bins[NCLS];
    __shared__ unsigned int scanbuf[256];
    __shared__ int          sres;
    __shared__ unsigned int s_kn;
    __shared__ int          s_is64;
    __shared__ float        s_red[8];

    int b = blockIdx.x, tid = threadIdx.x;
    int lane = tid & 31, wid = tid >> 5;

    for (int i = tid; i < NBINS; i += 256) hist[i] = 0u;
    if (tid < NCLS) bins[tid] = 0.f;
    if (tid < DIM / 2)
        *(float2*)(fvec + tid * 2) = *(const float2*)(features + (size_t)b * DIM + tid * 2);
    if (tid == 0) {
        s_kn = 0u;
        int is64 = 1;
        for (int i = 1; i < 128; i += 2)
            if (lab32[i] != 0) { is64 = 0; break; }
        s_is64 = is64;
    }
    __syncthreads();

    unsigned int raw = g_cnt[b];
    bool fb = (raw < 320u) || (raw > (unsigned)CAP);
    int kn = 0;

    if (!fb) {
        int nc = (int)raw;
        for (int i = tid; i < nc; i += 256) {
            float v = g_cd2[(size_t)b * CAP + i];
            scd2[i] = v;
            scidx[i] = g_cidx[(size_t)b * CAP + i];
            atomicAdd(&hist[bucket_of(v)], 1u);
        }
        __syncthreads();
        int Tk = bucket_rank(hist, scanbuf, &sres, KEEP, tid);
        for (int i = tid; i < nc; i += 256) {
            if (bucket_of(scd2[i]) <= Tk) {
                unsigned int p = atomicAdd(&s_kn, 1u);
                if (p < KMAX) kidx[p] = scidx[i];
            }
        }
        __syncthreads();
        kn = (int)s_kn;
        if (kn > KMAX) fb = true;
        __syncthreads();
        if (!fb) {
            float fn = g_fnorm[b];
            for (int c = wid; c < kn; c += 8) {
                const float4* crow = (const float4*)(centres + (size_t)kidx[c] * DIM);
                float4 cv = crow[lane];
                float4 fv = ((const float4*)fvec)[lane];
                float s1 = fv.x * cv.x + fv.y * cv.y + fv.z * cv.z + fv.w * cv.w;
                float s2 = cv.x * cv.x + cv.y * cv.y + cv.z * cv.z + cv.w * cv.w;
                #pragma unroll
                for (int o = 16; o; o >>= 1) {
                    s1 += __shfl_xor_sync(0xFFFFFFFFu, s1, o);
                    s2 += __shfl_xor_sync(0xFFFFFFFFu, s2, o);
                }
                if (!lane) kd2[c] = fn + s2 - 2.f * s1;
            }
            __syncthreads();
        }
    }

    if (fb) {
        // deterministic exact fallback over all centres
        for (int i = tid; i < NBINS; i += 256) hist[i] = 0u;
        if (tid == 0) s_kn = 0u;
        __syncthreads();
        float fn = g_fnorm[b];
        for (int i = tid; i < NCEN; i += 256) {
            const float4* crow = (const float4*)(centres + (size_t)i * DIM);
            float s1 = 0.f, s2 = 0.f;
            #pragma unroll 8
            for (int j = 0; j < 32; j++) {
                float4 cv = crow[j];
                float4 fv = ((const float4*)fvec)[j];
                s1 += fv.x * cv.x + fv.y * cv.y + fv.z * cv.z + fv.w * cv.w;
                s2 += cv.x * cv.x + cv.y * cv.y + cv.z * cv.z + cv.w * cv.w;
            }
            atomicAdd(&hist[bucket_of(fn + s2 - 2.f * s1)], 1u);
        }
        __syncthreads();
        int T2 = bucket_rank(hist, scanbuf, &sres, KEEP, tid);
        float edge2 = __uint_as_float((unsigned int)(T2 + 32513) << 15);
        for (int i = tid; i < NCEN; i += 256) {
            const float4* crow = (const float4*)(centres + (size_t)i * DIM);
            float s1 = 0.f, s2 = 0.f;
            #pragma unroll 8
            for (int j = 0; j < 32; j++) {
                float4 cv = crow[j];
                float4 fv = ((const float4*)fvec)[j];
                s1 += fv.x * cv.x + fv.y * cv.y + fv.z * cv.z + fv.w * cv.w;
                s2 += cv.x * cv.x + cv.y * cv.y + cv.z * cv.z + cv.w * cv.w;
            }
            float d2 = fn + s2 - 2.f * s1;
            if (d2 < edge2) {
                unsigned int p = atomicAdd(&s_kn, 1u);
                if (p < KMAX) { kd2[p] = d2; kidx[p] = i; }
            }
        }
        __syncthreads();
        kn = (int)min(s_kn, (unsigned)KMAX);
    }

    // --- exact top-KNN among kn (tie-break: smaller index, matching top_k)
    int is64 = s_is64;
    for (int t = tid; t < kn; t += 256) {
        float dt = kd2[t];
        int   it = kidx[t];
        int r = 0;
        for (int j = 0; j < kn; j++) {
            float dj = kd2[j];
            r += (dj < dt) || (dj == dt && kidx[j] < it);
        }
        if (r < KNN) {
            float w = expf(-dt * GC) * expf(wgt[it]);
            int l = lab32[is64 ? (it << 1) : it];
            atomicAdd(&bins[l], w);
        }
    }
    __syncthreads();

    float pv = 0.f;
    if (tid < NCLS) {
        pv = bins[tid];
        if (pv == 0.f) pv = 1e-10f;
    }
    float s = pv;
    #pragma unroll
    for (int o = 16; o; o >>= 1) s += __shfl_xor_sync(0xFFFFFFFFu, s, o);
    if ((tid & 31) == 0 && tid < NCLS) s_red[tid >> 5] = s;
    __syncthreads();
    if (tid == 0) s_red[0] = s_red[0] + s_red[1] + s_red[2] + s_red[3];
    __syncthreads();
    if (tid < NCLS)
        out[(size_t)b * NCLS + tid] = logf(pv / s_red[0]);
}

// ---------------- launch ----------------------------------------------------
extern "C" void kernel_launch(void* const* d_in, const int* in_sizes, int n_in,
                              void* d_out, int out_size) {
    const float* features = (const float*)d_in[0];
    const float* centres  = (const float*)d_in[1];
    const float* weight   = (const float*)d_in[2];
    const int*   labels   = (const int*)d_in[3];
    float* out = (float*)d_out;

    prep_kernel<<<BATCH / 8, 256>>>(features, 0);
    prep_kernel<<<NPAD / 8, 256>>>(centres, 1);

    cudaFuncSetAttribute(sample_mma_kernel,
                         cudaFuncAttributeMaxDynamicSharedMemorySize, SMT);
    cudaFuncSetAttribute(dist_mma_kernel,
                         cudaFuncAttributeMaxDynamicSharedMemorySize, SMT);

    sample_mma_kernel<<<dim3(BATCH / 128, NSAMP / 128), 512, SMT>>>();
    thresh_kernel<<<BATCH, 256>>>();
    dist_mma_kernel<<<dim3(BATCH / 128, NTILES / CHUNK), 512, SMT>>>();
    select_kernel<<<BATCH, 256>>>(features, centres, weight, labels, out);
}

// round 13
// speedup vs baseline: 1.3997x; 1.3997x over previous
#include <cuda_runtime.h>
#include <cuda_bf16.h>
#include <cstdint>

#define BATCH 1024
#define NCEN  100000
#define NPAD  100096          // 782 * 128
#define NTILES 782
#define SKIP  48              // sample tiles handled by thresh_kernel
#define DIM   128
#define KNN   200
#define NCLS  100
#define GC    0.005f

#define NSAMP 6144            // sample centres (48 n-tiles)
#define TSAMP 60              // sample rank for threshold
#define CAP   3072            // candidate list capacity per query
#define KEEP  240             // approx-rank keep target
#define KMAX  512             // kept-candidate buffer
#define NBINS 4096

// ---------------- device scratch -------------------------------------------
__device__ __nv_bfloat16 g_Ahi[BATCH * DIM];
__device__ __nv_bfloat16 g_Bhi[(size_t)NPAD * DIM];
__device__ float g_fnorm[BATCH];
__device__ float g_cnorm[NCEN];
__device__ float g_D2s[(size_t)BATCH * NSAMP];
__device__ float g_edge[BATCH];
__device__ unsigned int g_cnt[BATCH];
__device__ float g_cd2[(size_t)BATCH * CAP];
__device__ int   g_cidx[(size_t)BATCH * CAP];

// ---------------- helpers ---------------------------------------------------
__device__ __forceinline__ uint32_t smem_u32(const void* p) {
    uint32_t a;
    asm("{ .reg .u64 t; cvta.to.shared.u64 t, %1; cvt.u32.u64 %0, t; }"
        : "=r"(a) : "l"(p));
    return a;
}
__device__ __forceinline__ void ldsm4(uint32_t* r, uint32_t addr) {
    asm volatile("ldmatrix.sync.aligned.m8n8.x4.shared.b16 {%0,%1,%2,%3}, [%4];"
                 : "=r"(r[0]), "=r"(r[1]), "=r"(r[2]), "=r"(r[3]) : "r"(addr));
}
__device__ __forceinline__ void mma16816(float* d, const uint32_t* a,
                                         const uint32_t* b) {
    asm volatile(
        "mma.sync.aligned.m16n8k16.row.col.f32.bf16.bf16.f32 "
        "{%0,%1,%2,%3}, {%4,%5,%6,%7}, {%8,%9}, {%0,%1,%2,%3};"
        : "+f"(d[0]), "+f"(d[1]), "+f"(d[2]), "+f"(d[3])
        : "r"(a[0]), "r"(a[1]), "r"(a[2]), "r"(a[3]), "r"(b[0]), "r"(b[1]));
}
__device__ __forceinline__ void cp16(uint32_t dst, const void* src) {
    asm volatile("cp.async.cg.shared.global [%0], [%1], 16;"
                 :: "r"(dst), "l"(src) : "memory");
}
__device__ __forceinline__ int bucket_of(float v) {
    unsigned int u = __float_as_uint(v);
    if ((int)u <= 0) return 0;
    int b = (int)(u >> 15) - 32512;
    return b < 0 ? 0 : (b > NBINS - 1 ? NBINS - 1 : b);
}
// block-wide (256 threads): smallest bucket T with cum(hist[0..T]) >= rank
__device__ int bucket_rank(unsigned int* hist, unsigned int* scanbuf,
                           int* sres, int rank, int tid) {
    unsigned int ls = 0;
    int base = tid * (NBINS / 256);
    #pragma unroll
    for (int j = 0; j < NBINS / 256; j++) ls += hist[base + j];
    scanbuf[tid] = ls;
    __syncthreads();
    for (int off = 1; off < 256; off <<= 1) {
        unsigned int v = (tid >= off) ? scanbuf[tid - off] : 0u;
        __syncthreads();
        scanbuf[tid] += v;
        __syncthreads();
    }
    unsigned int incl = scanbuf[tid], excl = incl - ls;
    if (excl < (unsigned)rank && incl >= (unsigned)rank) {
        unsigned int c = excl;
        for (int j = 0; j < NBINS / 256; j++) {
            c += hist[base + j];
            if (c >= (unsigned)rank) { *sres = base + j; break; }
        }
    }
    __syncthreads();
    return *sres;
}
__device__ __forceinline__ void push_cand(int m, float v, int n) {
    unsigned int p = atomicAdd(&g_cnt[m], 1u);
    if (p < CAP) {
        g_cd2[(size_t)m * CAP + p] = v;
        g_cidx[(size_t)m * CAP + p] = n;
    }
}

// ---------------- fused prep: norms + hi bf16 + zero cnt --------------------
#define NBLK_B (NPAD / 8)
#define NBLK_A (BATCH / 8)
__global__ void prep_kernel(const float* __restrict__ feat,
                            const float* __restrict__ cent) {
    int bx = blockIdx.x;
    int tid = threadIdx.x, lane = tid & 31;
    bool isB = (bx < NBLK_B);
    int w = (isB ? bx : bx - NBLK_B) * 8 + (tid >> 5);
    if (!isB) {
        if (tid < 8) g_cnt[(bx - NBLK_B) * 8 + tid] = 0u;
        if (w >= BATCH) return;
    } else if (w >= NPAD) return;

    const float* src = isB ? cent : feat;
    __nv_bfloat16* dst = isB ? g_Bhi : g_Ahi;
    float4 v = make_float4(0.f, 0.f, 0.f, 0.f);
    if (!isB || w < NCEN) v = ((const float4*)(src + (size_t)w * DIM))[lane];
    float s = v.x * v.x + v.y * v.y + v.z * v.z + v.w * v.w;
    #pragma unroll
    for (int o = 16; o; o >>= 1) s += __shfl_xor_sync(0xFFFFFFFFu, s, o);
    if (!lane) {
        if (isB) { if (w < NCEN) g_cnorm[w] = s; }
        else g_fnorm[w] = s;
    }
    float f[4] = { v.x, v.y, v.z, v.w };
    ushort4 ph;
    unsigned short* hp = &ph.x;
    #pragma unroll
    for (int i = 0; i < 4; i++) {
        __nv_bfloat16 h = __float2bfloat16(f[i]);
        hp[i] = *(unsigned short*)&h;
    }
    ((ushort4*)(dst + (size_t)w * DIM))[lane] = ph;
}

// ---------------- GEMM bodies ------------------------------------------------
// smem: A @ 0 (32 KB), B @ 32768. 64 KB total -> 2 CTAs/SM.
#define SMT 65536
__device__ __forceinline__ uint32_t swoff(int row, int chunk) {
    return (uint32_t)(row * 256 + ((chunk ^ (row & 7)) << 4));
}

struct WarpGeom {
    int wm, wn, rowA, cgA, sxA, rowB, cgB, sxB, qrow, qcol;
};
__device__ __forceinline__ WarpGeom geom(int tid) {
    WarpGeom w;
    int lane = tid & 31, wid = tid >> 5;
    w.wm = (wid & 3) * 32;
    w.wn = (wid >> 2) * 32;
    int g = lane >> 3, l7 = lane & 7;
    w.rowA = w.wm + ((g & 1) << 3) + l7;
    w.cgA  = g >> 1;
    w.sxA  = w.rowA & 7;
    w.rowB = w.wn + ((g >> 1) << 3) + l7;
    w.cgB  = g & 1;
    w.sxB  = w.rowB & 7;
    w.qrow = lane >> 2;
    w.qcol = (lane & 3) << 1;
    return w;
}

__device__ __forceinline__ void compute_tile(uint32_t sb, uint32_t bbase,
                                             const WarpGeom& w,
                                             float acc[2][4][4]) {
    #pragma unroll
    for (int mt = 0; mt < 2; mt++)
        #pragma unroll
        for (int nt = 0; nt < 4; nt++)
            #pragma unroll
            for (int r = 0; r < 4; r++) acc[mt][nt][r] = 0.f;
    #pragma unroll
    for (int ks = 0; ks < 8; ks++) {
        int c0 = ks * 2;
        uint32_t afr[2][4], bfr[2][4];
        #pragma unroll
        for (int mt = 0; mt < 2; mt++)
            ldsm4(afr[mt], sb + (uint32_t)((w.rowA + mt * 16) * 256
                                 + (((c0 + w.cgA) ^ w.sxA) << 4)));
        #pragma unroll
        for (int ng = 0; ng < 2; ng++)
            ldsm4(bfr[ng], bbase + (uint32_t)((w.rowB + ng * 16) * 256
                                 + (((c0 + w.cgB) ^ w.sxB) << 4)));
        #pragma unroll
        for (int mt = 0; mt < 2; mt++)
            #pragma unroll
            for (int nt = 0; nt < 4; nt++)
                mma16816(acc[mt][nt], afr[mt], &bfr[nt >> 1][(nt & 1) * 2]);
    }
}

__device__ __forceinline__ void stage_ab(uint32_t sb, int bm, int bn, int tid) {
    #pragma unroll
    for (int it = 0; it < 4; it++) {
        int q = it * 512 + tid;
        int row = q >> 4, chunk = q & 15;
        uint32_t so = swoff(row, chunk);
        cp16(sb + so,          g_Ahi + (size_t)(bm + row) * DIM + (chunk << 3));
        cp16(sb + 32768u + so, g_Bhi + (size_t)(bn + row) * DIM + (chunk << 3));
    }
    asm volatile("cp.async.commit_group;" ::: "memory");
    asm volatile("cp.async.wait_group 0;" ::: "memory");
}

// sample GEMM: one tile per CTA, store approx d2 rows
__global__ __launch_bounds__(512, 2)
void sample_mma_kernel() {
    extern __shared__ char smem[];
    uint32_t sb = smem_u32(smem);
    const int tid = threadIdx.x;
    const int bm = blockIdx.x * 128;
    const int bn = blockIdx.y * 128;
    WarpGeom w = geom(tid);

    stage_ab(sb, bm, bn, tid);
    __syncthreads();

    float acc[2][4][4];
    compute_tile(sb, sb + 32768u, w, acc);

    #pragma unroll
    for (int nt = 0; nt < 4; nt++) {
        int n = bn + w.wn + nt * 8 + w.qcol;
        float2 cn = *(const float2*)(g_cnorm + n);
        #pragma unroll
        for (int mt = 0; mt < 2; mt++) {
            int m0 = bm + w.wm + mt * 16 + w.qrow;
            float fn0 = g_fnorm[m0], fn1 = g_fnorm[m0 + 8];
            *(float2*)(g_D2s + (size_t)m0 * NSAMP + n) =
                make_float2(fn0 + cn.x - 2.f * acc[mt][nt][0],
                            fn0 + cn.y - 2.f * acc[mt][nt][1]);
            *(float2*)(g_D2s + (size_t)(m0 + 8) * NSAMP + n) =
                make_float2(fn1 + cn.x - 2.f * acc[mt][nt][2],
                            fn1 + cn.y - 2.f * acc[mt][nt][3]);
        }
    }
}

// ---------------- threshold kernel (also pushes sample-region candidates) ---
__global__ __launch_bounds__(256)
void thresh_kernel() {
    __shared__ unsigned int hist[NBINS];
    __shared__ unsigned int scanbuf[256];
    __shared__ int sres;
    int b = blockIdx.x, tid = threadIdx.x;
    for (int i = tid; i < NBINS; i += 256) hist[i] = 0u;
    __syncthreads();
    const float* row = g_D2s + (size_t)b * NSAMP;
    for (int s = tid; s < NSAMP; s += 256)
        atomicAdd(&hist[bucket_of(row[s])], 1u);
    __syncthreads();
    int T = bucket_rank(hist, scanbuf, &sres, TSAMP, tid);
    float edge = __uint_as_float((unsigned int)(T + 32513) << 15);
    if (tid == 0) g_edge[b] = edge;
    // push candidates from the sample region (dist skips tiles 0..SKIP-1)
    for (int s = tid; s < NSAMP; s += 256) {
        float v = row[s];
        if (v < edge) push_cand(b, v, s);
    }
}

// main GEMM: one tile per CTA over tiles SKIP..NTILES-1, filter epilogue
__global__ __launch_bounds__(512, 2)
void dist_mma_kernel() {
    extern __shared__ char smem[];
    uint32_t sb = smem_u32(smem);
    const int tid = threadIdx.x;
    const int bm = blockIdx.x * 128;   // m fastest: m-CTAs share B via L2
    const int bn = (SKIP + blockIdx.y) * 128;
    WarpGeom w = geom(tid);

    stage_ab(sb, bm, bn, tid);
    __syncthreads();

    float acc[2][4][4];
    compute_tile(sb, sb + 32768u, w, acc);

    // hoisted per-thread row constants
    float fnv[2][2], edv[2][2];
    #pragma unroll
    for (int mt = 0; mt < 2; mt++) {
        int m0 = bm + w.wm + mt * 16 + w.qrow;
        fnv[mt][0] = g_fnorm[m0];  fnv[mt][1] = g_fnorm[m0 + 8];
        edv[mt][0] = g_edge[m0];   edv[mt][1] = g_edge[m0 + 8];
    }

    #pragma unroll
    for (int nt = 0; nt < 4; nt++) {
        int n = bn + w.wn + nt * 8 + w.qcol;      // even => n+1 valid too
        if (n >= NCEN) continue;
        float2 cn = *(const float2*)(g_cnorm + n);
        #pragma unroll
        for (int mt = 0; mt < 2; mt++) {
            int m0 = bm + w.wm + mt * 16 + w.qrow;
            float v0 = fnv[mt][0] + cn.x - 2.f * acc[mt][nt][0];
            float v1 = fnv[mt][0] + cn.y - 2.f * acc[mt][nt][1];
            float v2 = fnv[mt][1] + cn.x - 2.f * acc[mt][nt][2];
            float v3 = fnv[mt][1] + cn.y - 2.f * acc[mt][nt][3];
            if (v0 < edv[mt][0]) push_cand(m0, v0, n);
            if (v1 < edv[mt][0]) push_cand(m0, v1, n + 1);
            if (v2 < edv[mt][1]) push_cand(m0 + 8, v2, n);
            if (v3 < edv[mt][1]) push_cand(m0 + 8, v3, n + 1);
        }
    }
}

// ---------------- selection: candidates -> exact top-200 -> logprobs --------
__global__ __launch_bounds__(256)
void select_kernel(const float* __restrict__ features,
                   const float* __restrict__ centres,
                   const float* __restrict__ wgt,
                   const int*   __restrict__ lab32,
                   float*       __restrict__ out) {
    __shared__ float        scd2[CAP];
    __shared__ int          scidx[CAP];
    __shared__ unsigned int hist[NBINS];
    __shared__ float        kd2[KMAX];
    __shared__ int          kidx[KMAX];
    __shared__ float        fvec[DIM];
    __shared__ float        bins[NCLS];
    __shared__ unsigned int scanbuf[256];
    __shared__ int          sres;
    __shared__ unsigned int s_kn;
    __shared__ int          s_is64;
    __shared__ float        s_red[8];

    int b = blockIdx.x, tid = threadIdx.x;
    int lane = tid & 31, wid = tid >> 5;

    for (int i = tid; i < NBINS; i += 256) hist[i] = 0u;
    if (tid < NCLS) bins[tid] = 0.f;
    if (tid < DIM / 2)
        *(float2*)(fvec + tid * 2) = *(const float2*)(features + (size_t)b * DIM + tid * 2);
    if (tid == 0) {
        s_kn = 0u;
        int is64 = 1;
        for (int i = 1; i < 128; i += 2)
            if (lab32[i] != 0) { is64 = 0; break; }
        s_is64 = is64;
    }
    __syncthreads();

    unsigned int raw = g_cnt[b];
    bool fb = (raw < 320u) || (raw > (unsigned)CAP);
    int kn = 0;

    if (!fb) {
        int nc = (int)raw;
        for (int i = tid; i < nc; i += 256) {
            float v = g_cd2[(size_t)b * CAP + i];
            scd2[i] = v;
            scidx[i] = g_cidx[(size_t)b * CAP + i];
            atomicAdd(&hist[bucket_of(v)], 1u);
        }
        __syncthreads();
        int Tk = bucket_rank(hist, scanbuf, &sres, KEEP, tid);
        for (int i = tid; i < nc; i += 256) {
            if (bucket_of(scd2[i]) <= Tk) {
                unsigned int p = atomicAdd(&s_kn, 1u);
                if (p < KMAX) kidx[p] = scidx[i];
            }
        }
        __syncthreads();
        kn = (int)s_kn;
        if (kn > KMAX) fb = true;
        __syncthreads();
        if (!fb) {
            float fn = g_fnorm[b];
            for (int c = wid; c < kn; c += 8) {
                const float4* crow = (const float4*)(centres + (size_t)kidx[c] * DIM);
                float4 cv = crow[lane];
                float4 fv = ((const float4*)fvec)[lane];
                float s1 = fv.x * cv.x + fv.y * cv.y + fv.z * cv.z + fv.w * cv.w;
                float s2 = cv.x * cv.x + cv.y * cv.y + cv.z * cv.z + cv.w * cv.w;
                #pragma unroll
                for (int o = 16; o; o >>= 1) {
                    s1 += __shfl_xor_sync(0xFFFFFFFFu, s1, o);
                    s2 += __shfl_xor_sync(0xFFFFFFFFu, s2, o);
                }
                if (!lane) kd2[c] = fn + s2 - 2.f * s1;
            }
            __syncthreads();
        }
    }

    if (fb) {
        // deterministic exact fallback over all centres
        for (int i = tid; i < NBINS; i += 256) hist[i] = 0u;
        if (tid == 0) s_kn = 0u;
        __syncthreads();
        float fn = g_fnorm[b];
        for (int i = tid; i < NCEN; i += 256) {
            const float4* crow = (const float4*)(centres + (size_t)i * DIM);
            float s1 = 0.f, s2 = 0.f;
            #pragma unroll 8
            for (int j = 0; j < 32; j++) {
                float4 cv = crow[j];
                float4 fv = ((const float4*)fvec)[j];
                s1 += fv.x * cv.x + fv.y * cv.y + fv.z * cv.z + fv.w * cv.w;
                s2 += cv.x * cv.x + cv.y * cv.y + cv.z * cv.z + cv.w * cv.w;
            }
            atomicAdd(&hist[bucket_of(fn + s2 - 2.f * s1)], 1u);
        }
        __syncthreads();
        int T2 = bucket_rank(hist, scanbuf, &sres, KEEP, tid);
        float edge2 = __uint_as_float((unsigned int)(T2 + 32513) << 15);
        for (int i = tid; i < NCEN; i += 256) {
            const float4* crow = (const float4*)(centres + (size_t)i * DIM);
            float s1 = 0.f, s2 = 0.f;
            #pragma unroll 8
            for (int j = 0; j < 32; j++) {
                float4 cv = crow[j];
                float4 fv = ((const float4*)fvec)[j];
                s1 += fv.x * cv.x + fv.y * cv.y + fv.z * cv.z + fv.w * cv.w;
                s2 += cv.x * cv.x + cv.y * cv.y + cv.z * cv.z + cv.w * cv.w;
            }
            float d2 = fn + s2 - 2.f * s1;
            if (d2 < edge2) {
                unsigned int p = atomicAdd(&s_kn, 1u);
                if (p < KMAX) { kd2[p] = d2; kidx[p] = i; }
            }
        }
        __syncthreads();
        kn = (int)min(s_kn, (unsigned)KMAX);
    }

    // --- exact top-KNN among kn (tie-break: smaller index, matching top_k)
    int is64 = s_is64;
    for (int t = tid; t < kn; t += 256) {
        float dt = kd2[t];
        int   it = kidx[t];
        int r = 0;
        for (int j = 0; j < kn; j++) {
            float dj = kd2[j];
            r += (dj < dt) || (dj == dt && kidx[j] < it);
        }
        if (r < KNN) {
            float w = expf(-dt * GC) * expf(wgt[it]);
            int l = lab32[is64 ? (it << 1) : it];
            atomicAdd(&bins[l], w);
        }
    }
    __syncthreads();

    float pv = 0.f;
    if (tid < NCLS) {
        pv = bins[tid];
        if (pv == 0.f) pv = 1e-10f;
    }
    float s = pv;
    #pragma unroll
    for (int o = 16; o; o >>= 1) s += __shfl_xor_sync(0xFFFFFFFFu, s, o);
    if ((tid & 31) == 0 && tid < NCLS) s_red[tid >> 5] = s;
    __syncthreads();
    if (tid == 0) s_red[0] = s_red[0] + s_red[1] + s_red[2] + s_red[3];
    __syncthreads();
    if (tid < NCLS)
        out[(size_t)b * NCLS + tid] = logf(pv / s_red[0]);
}

// ---------------- launch ----------------------------------------------------
extern "C" void kernel_launch(void* const* d_in, const int* in_sizes, int n_in,
                              void* d_out, int out_size) {
    const float* features = (const float*)d_in[0];
    const float* centres  = (const float*)d_in[1];
    const float* weight   = (const float*)d_in[2];
    const int*   labels   = (const int*)d_in[3];
    float* out = (float*)d_out;

    prep_kernel<<<NBLK_B + NBLK_A, 256>>>(features, centres);

    cudaFuncSetAttribute(sample_mma_kernel,
                         cudaFuncAttributeMaxDynamicSharedMemorySize, SMT);
    cudaFuncSetAttribute(dist_mma_kernel,
                         cudaFuncAttributeMaxDynamicSharedMemorySize, SMT);

    sample_mma_kernel<<<dim3(BATCH / 128, NSAMP / 128), 512, SMT>>>();
    thresh_kernel<<<BATCH, 256>>>();
    dist_mma_kernel<<<dim3(BATCH / 128, NTILES - SKIP), 512, SMT>>>();
    select_kernel<<<BATCH, 256>>>(features, centres, weight, labels, out);
}

// round 14
// speedup vs baseline: 1.4803x; 1.0575x over previous
#include <cuda_runtime.h>
#include <cuda_bf16.h>
#include <cstdint>

#define BATCH 1024
#define NCEN  100000
#define NPAD  100096          // 1564 * 64
#define NT64  1564            // 64-wide n-tiles
#define SKIP64 96             // sample tiles (96*64 = 6144) handled by thresh
#define DIM   128
#define KNN   200
#define NCLS  100
#define GC    0.005f

#define NSAMP 6144
#define TSAMP 60
#define CAP   3072
#define KEEP  240
#define KMAX  512
#define NBINS 4096

// ---------------- device scratch -------------------------------------------
__device__ __nv_bfloat16 g_Ahi[BATCH * DIM];
__device__ __nv_bfloat16 g_Bhi[(size_t)NPAD * DIM];
__device__ float g_fnorm[BATCH];
__device__ float g_cnorm[NCEN];
__device__ float g_D2s[(size_t)BATCH * NSAMP];
__device__ float g_edge[BATCH];
__device__ unsigned int g_cnt[BATCH];
__device__ float g_cd2[(size_t)BATCH * CAP];
__device__ int   g_cidx[(size_t)BATCH * CAP];

// ---------------- helpers ---------------------------------------------------
__device__ __forceinline__ uint32_t smem_u32(const void* p) {
    uint32_t a;
    asm("{ .reg .u64 t; cvta.to.shared.u64 t, %1; cvt.u32.u64 %0, t; }"
        : "=r"(a) : "l"(p));
    return a;
}
__device__ __forceinline__ void ldsm4(uint32_t* r, uint32_t addr) {
    asm volatile("ldmatrix.sync.aligned.m8n8.x4.shared.b16 {%0,%1,%2,%3}, [%4];"
                 : "=r"(r[0]), "=r"(r[1]), "=r"(r[2]), "=r"(r[3]) : "r"(addr));
}
__device__ __forceinline__ void mma16816(float* d, const uint32_t* a,
                                         const uint32_t* b) {
    asm volatile(
        "mma.sync.aligned.m16n8k16.row.col.f32.bf16.bf16.f32 "
        "{%0,%1,%2,%3}, {%4,%5,%6,%7}, {%8,%9}, {%0,%1,%2,%3};"
        : "+f"(d[0]), "+f"(d[1]), "+f"(d[2]), "+f"(d[3])
        : "r"(a[0]), "r"(a[1]), "r"(a[2]), "r"(a[3]), "r"(b[0]), "r"(b[1]));
}
__device__ __forceinline__ void cp16(uint32_t dst, const void* src) {
    asm volatile("cp.async.cg.shared.global [%0], [%1], 16;"
                 :: "r"(dst), "l"(src) : "memory");
}
__device__ __forceinline__ int bucket_of(float v) {
    unsigned int u = __float_as_uint(v);
    if ((int)u <= 0) return 0;
    int b = (int)(u >> 15) - 32512;
    return b < 0 ? 0 : (b > NBINS - 1 ? NBINS - 1 : b);
}
// block-wide (256 threads): smallest bucket T with cum(hist[0..T]) >= rank
__device__ int bucket_rank(unsigned int* hist, unsigned int* scanbuf,
                           int* sres, int rank, int tid) {
    unsigned int ls = 0;
    int base = tid * (NBINS / 256);
    #pragma unroll
    for (int j = 0; j < NBINS / 256; j++) ls += hist[base + j];
    scanbuf[tid] = ls;
    __syncthreads();
    for (int off = 1; off < 256; off <<= 1) {
        unsigned int v = (tid >= off) ? scanbuf[tid - off] : 0u;
        __syncthreads();
        scanbuf[tid] += v;
        __syncthreads();
    }
    unsigned int incl = scanbuf[tid], excl = incl - ls;
    if (excl < (unsigned)rank && incl >= (unsigned)rank) {
        unsigned int c = excl;
        for (int j = 0; j < NBINS / 256; j++) {
            c += hist[base + j];
            if (c >= (unsigned)rank) { *sres = base + j; break; }
        }
    }
    __syncthreads();
    return *sres;
}
__device__ __forceinline__ void push_cand(int m, float v, int n) {
    unsigned int p = atomicAdd(&g_cnt[m], 1u);
    if (p < CAP) {
        g_cd2[(size_t)m * CAP + p] = v;
        g_cidx[(size_t)m * CAP + p] = n;
    }
}

// ---------------- fused prep: norms + hi bf16 + zero cnt --------------------
#define NBLK_B (NPAD / 8)
#define NBLK_A (BATCH / 8)
__global__ void prep_kernel(const float* __restrict__ feat,
                            const float* __restrict__ cent) {
    int bx = blockIdx.x;
    int tid = threadIdx.x, lane = tid & 31;
    bool isB = (bx < NBLK_B);
    int w = (isB ? bx : bx - NBLK_B) * 8 + (tid >> 5);
    if (!isB) {
        if (tid < 8) g_cnt[(bx - NBLK_B) * 8 + tid] = 0u;
        if (w >= BATCH) return;
    } else if (w >= NPAD) return;

    const float* src = isB ? cent : feat;
    __nv_bfloat16* dst = isB ? g_Bhi : g_Ahi;
    float4 v = make_float4(0.f, 0.f, 0.f, 0.f);
    if (!isB || w < NCEN) v = ((const float4*)(src + (size_t)w * DIM))[lane];
    float s = v.x * v.x + v.y * v.y + v.z * v.z + v.w * v.w;
    #pragma unroll
    for (int o = 16; o; o >>= 1) s += __shfl_xor_sync(0xFFFFFFFFu, s, o);
    if (!lane) {
        if (isB) { if (w < NCEN) g_cnorm[w] = s; }
        else g_fnorm[w] = s;
    }
    float f[4] = { v.x, v.y, v.z, v.w };
    ushort4 ph;
    unsigned short* hp = &ph.x;
    #pragma unroll
    for (int i = 0; i < 4; i++) {
        __nv_bfloat16 h = __float2bfloat16(f[i]);
        hp[i] = *(unsigned short*)&h;
    }
    ((ushort4*)(dst + (size_t)w * DIM))[lane] = ph;
}

// ---------------- GEMM bodies: 128m x 64n tile, 256 threads, 4 CTA/SM -------
// smem: A @ 0 (32 KB), B @ 32768 (16 KB). 48 KB total.
#define SMT 49152
__device__ __forceinline__ uint32_t swoff(int row, int chunk) {
    return (uint32_t)(row * 256 + ((chunk ^ (row & 7)) << 4));
}

struct WarpGeom {
    int wm, wn, rowA, cgA, sxA, rowB, cgB, sxB, qrow, qcol;
};
__device__ __forceinline__ WarpGeom geom(int tid) {
    WarpGeom w;
    int lane = tid & 31, wid = tid >> 5;     // 8 warps: 4m x 2n
    w.wm = (wid & 3) * 32;
    w.wn = (wid >> 2) * 32;
    int g = lane >> 3, l7 = lane & 7;
    w.rowA = w.wm + ((g & 1) << 3) + l7;
    w.cgA  = g >> 1;
    w.sxA  = w.rowA & 7;
    w.rowB = w.wn + ((g >> 1) << 3) + l7;
    w.cgB  = g & 1;
    w.sxB  = w.rowB & 7;
    w.qrow = lane >> 2;
    w.qcol = (lane & 3) << 1;
    return w;
}

__device__ __forceinline__ void compute_tile(uint32_t sb, uint32_t bbase,
                                             const WarpGeom& w,
                                             float acc[2][4][4]) {
    #pragma unroll
    for (int mt = 0; mt < 2; mt++)
        #pragma unroll
        for (int nt = 0; nt < 4; nt++)
            #pragma unroll
            for (int r = 0; r < 4; r++) acc[mt][nt][r] = 0.f;
    #pragma unroll
    for (int ks = 0; ks < 8; ks++) {
        int c0 = ks * 2;
        uint32_t afr[2][4], bfr[2][4];
        #pragma unroll
        for (int mt = 0; mt < 2; mt++)
            ldsm4(afr[mt], sb + (uint32_t)((w.rowA + mt * 16) * 256
                                 + (((c0 + w.cgA) ^ w.sxA) << 4)));
        #pragma unroll
        for (int ng = 0; ng < 2; ng++)
            ldsm4(bfr[ng], bbase + (uint32_t)((w.rowB + ng * 16) * 256
                                 + (((c0 + w.cgB) ^ w.sxB) << 4)));
        #pragma unroll
        for (int mt = 0; mt < 2; mt++)
            #pragma unroll
            for (int nt = 0; nt < 4; nt++)
                mma16816(acc[mt][nt], afr[mt], &bfr[nt >> 1][(nt & 1) * 2]);
    }
}

// stage A (128 rows) + B (64 rows), 256 threads, 12 cp16 each
__device__ __forceinline__ void stage_ab(uint32_t sb, int bm, int bn, int tid) {
    #pragma unroll
    for (int it = 0; it < 8; it++) {
        int q = it * 256 + tid;
        int row = q >> 4, chunk = q & 15;
        cp16(sb + swoff(row, chunk),
             g_Ahi + (size_t)(bm + row) * DIM + (chunk << 3));
    }
    #pragma unroll
    for (int it = 0; it < 4; it++) {
        int q = it * 256 + tid;
        int row = q >> 4, chunk = q & 15;
        cp16(sb + 32768u + swoff(row, chunk),
             g_Bhi + (size_t)(bn + row) * DIM + (chunk << 3));
    }
    asm volatile("cp.async.commit_group;" ::: "memory");
    asm volatile("cp.async.wait_group 0;" ::: "memory");
}

// sample GEMM: one 128x64 tile per CTA, store approx d2 rows
__global__ __launch_bounds__(256, 4)
void sample_mma_kernel() {
    extern __shared__ char smem[];
    uint32_t sb = smem_u32(smem);
    const int tid = threadIdx.x;
    const int bm = blockIdx.x * 128;
    const int bn = blockIdx.y * 64;
    WarpGeom w = geom(tid);

    stage_ab(sb, bm, bn, tid);
    __syncthreads();

    float acc[2][4][4];
    compute_tile(sb, sb + 32768u, w, acc);

    #pragma unroll
    for (int nt = 0; nt < 4; nt++) {
        int n = bn + w.wn + nt * 8 + w.qcol;
        float2 cn = *(const float2*)(g_cnorm + n);
        #pragma unroll
        for (int mt = 0; mt < 2; mt++) {
            int m0 = bm + w.wm + mt * 16 + w.qrow;
            float fn0 = g_fnorm[m0], fn1 = g_fnorm[m0 + 8];
            *(float2*)(g_D2s + (size_t)m0 * NSAMP + n) =
                make_float2(fn0 + cn.x - 2.f * acc[mt][nt][0],
                            fn0 + cn.y - 2.f * acc[mt][nt][1]);
            *(float2*)(g_D2s + (size_t)(m0 + 8) * NSAMP + n) =
                make_float2(fn1 + cn.x - 2.f * acc[mt][nt][2],
                            fn1 + cn.y - 2.f * acc[mt][nt][3]);
        }
    }
}

// ---------------- threshold kernel (also pushes sample-region candidates) ---
__global__ __launch_bounds__(256)
void thresh_kernel() {
    __shared__ unsigned int hist[NBINS];
    __shared__ unsigned int scanbuf[256];
    __shared__ int sres;
    int b = blockIdx.x, tid = threadIdx.x;
    for (int i = tid; i < NBINS; i += 256) hist[i] = 0u;
    __syncthreads();
    const float* row = g_D2s + (size_t)b * NSAMP;
    for (int s = tid; s < NSAMP; s += 256)
        atomicAdd(&hist[bucket_of(row[s])], 1u);
    __syncthreads();
    int T = bucket_rank(hist, scanbuf, &sres, TSAMP, tid);
    float edge = __uint_as_float((unsigned int)(T + 32513) << 15);
    if (tid == 0) g_edge[b] = edge;
    for (int s = tid; s < NSAMP; s += 256) {
        float v = row[s];
        if (v < edge) push_cand(b, v, s);
    }
}

// main GEMM: one 128x64 tile per CTA over tiles SKIP64..NT64-1
__global__ __launch_bounds__(256, 4)
void dist_mma_kernel() {
    extern __shared__ char smem[];
    uint32_t sb = smem_u32(smem);
    const int tid = threadIdx.x;
    const int bm = blockIdx.x * 128;   // m fastest: m-CTAs share B via L2
    const int bn = (SKIP64 + blockIdx.y) * 64;
    WarpGeom w = geom(tid);

    stage_ab(sb, bm, bn, tid);
    __syncthreads();

    float acc[2][4][4];
    compute_tile(sb, sb + 32768u, w, acc);

    float fnv[2][2], edv[2][2];
    #pragma unroll
    for (int mt = 0; mt < 2; mt++) {
        int m0 = bm + w.wm + mt * 16 + w.qrow;
        fnv[mt][0] = g_fnorm[m0];  fnv[mt][1] = g_fnorm[m0 + 8];
        edv[mt][0] = g_edge[m0];   edv[mt][1] = g_edge[m0 + 8];
    }

    #pragma unroll
    for (int nt = 0; nt < 4; nt++) {
        int n = bn + w.wn + nt * 8 + w.qcol;      // even => n+1 valid too
        if (n >= NCEN) continue;
        float2 cn = *(const float2*)(g_cnorm + n);
        #pragma unroll
        for (int mt = 0; mt < 2; mt++) {
            int m0 = bm + w.wm + mt * 16 + w.qrow;
            float v0 = fnv[mt][0] + cn.x - 2.f * acc[mt][nt][0];
            float v1 = fnv[mt][0] + cn.y - 2.f * acc[mt][nt][1];
            float v2 = fnv[mt][1] + cn.x - 2.f * acc[mt][nt][2];
            float v3 = fnv[mt][1] + cn.y - 2.f * acc[mt][nt][3];
            if (v0 < edv[mt][0]) push_cand(m0, v0, n);
            if (v1 < edv[mt][0]) push_cand(m0, v1, n + 1);
            if (v2 < edv[mt][1]) push_cand(m0 + 8, v2, n);
            if (v3 < edv[mt][1]) push_cand(m0 + 8, v3, n + 1);
        }
    }
}

// ---------------- selection: candidates -> exact top-200 -> logprobs --------
__global__ __launch_bounds__(256)
void select_kernel(const float* __restrict__ features,
                   const float* __restrict__ centres,
                   const float* __restrict__ wgt,
                   const int*   __restrict__ lab32,
                   float*       __restrict__ out) {
    __shared__ float        scd2[CAP];
    __shared__ int          scidx[CAP];
    __shared__ unsigned int hist[NBINS];
    __shared__ float        kd2[KMAX];
    __shared__ int          kidx[KMAX];
    __shared__ float        fvec[DIM];
    __shared__ float        bins[NCLS];
    __shared__ unsigned int scanbuf[256];
    __shared__ int          sres;
    __shared__ unsigned int s_kn;
    __shared__ int          s_is64;
    __shared__ float        s_red[8];

    int b = blockIdx.x, tid = threadIdx.x;
    int lane = tid & 31, wid = tid >> 5;

    for (int i = tid; i < NBINS; i += 256) hist[i] = 0u;
    if (tid < NCLS) bins[tid] = 0.f;
    if (tid < DIM / 2)
        *(float2*)(fvec + tid * 2) = *(const float2*)(features + (size_t)b * DIM + tid * 2);
    if (tid == 0) {
        s_kn = 0u;
        int is64 = 1;
        for (int i = 1; i < 128; i += 2)
            if (lab32[i] != 0) { is64 = 0; break; }
        s_is64 = is64;
    }
    __syncthreads();

    unsigned int raw = g_cnt[b];
    bool fb = (raw < 320u) || (raw > (unsigned)CAP);
    int kn = 0;

    if (!fb) {
        int nc = (int)raw;
        for (int i = tid; i < nc; i += 256) {
            float v = g_cd2[(size_t)b * CAP + i];
            scd2[i] = v;
            scidx[i] = g_cidx[(size_t)b * CAP + i];
            atomicAdd(&hist[bucket_of(v)], 1u);
        }
        __syncthreads();
        int Tk = bucket_rank(hist, scanbuf, &sres, KEEP, tid);
        for (int i = tid; i < nc; i += 256) {
            if (bucket_of(scd2[i]) <= Tk) {
                unsigned int p = atomicAdd(&s_kn, 1u);
                if (p < KMAX) kidx[p] = scidx[i];
            }
        }
        __syncthreads();
        kn = (int)s_kn;
        if (kn > KMAX) fb = true;
        __syncthreads();
        if (!fb) {
            float fn = g_fnorm[b];
            for (int c = wid; c < kn; c += 8) {
                const float4* crow = (const float4*)(centres + (size_t)kidx[c] * DIM);
                float4 cv = crow[lane];
                float4 fv = ((const float4*)fvec)[lane];
                float s1 = fv.x * cv.x + fv.y * cv.y + fv.z * cv.z + fv.w * cv.w;
                float s2 = cv.x * cv.x + cv.y * cv.y + cv.z * cv.z + cv.w * cv.w;
                #pragma unroll
                for (int o = 16; o; o >>= 1) {
                    s1 += __shfl_xor_sync(0xFFFFFFFFu, s1, o);
                    s2 += __shfl_xor_sync(0xFFFFFFFFu, s2, o);
                }
                if (!lane) kd2[c] = fn + s2 - 2.f * s1;
            }
            __syncthreads();
        }
    }

    if (fb) {
        // deterministic exact fallback over all centres
        for (int i = tid; i < NBINS; i += 256) hist[i] = 0u;
        if (tid == 0) s_kn = 0u;
        __syncthreads();
        float fn = g_fnorm[b];
        for (int i = tid; i < NCEN; i += 256) {
            const float4* crow = (const float4*)(centres + (size_t)i * DIM);
            float s1 = 0.f, s2 = 0.f;
            #pragma unroll 8
            for (int j = 0; j < 32; j++) {
                float4 cv = crow[j];
                float4 fv = ((const float4*)fvec)[j];
                s1 += fv.x * cv.x + fv.y * cv.y + fv.z * cv.z + fv.w * cv.w;
                s2 += cv.x * cv.x + cv.y * cv.y + cv.z * cv.z + cv.w * cv.w;
            }
            atomicAdd(&hist[bucket_of(fn + s2 - 2.f * s1)], 1u);
        }
        __syncthreads();
        int T2 = bucket_rank(hist, scanbuf, &sres, KEEP, tid);
        float edge2 = __uint_as_float((unsigned int)(T2 + 32513) << 15);
        for (int i = tid; i < NCEN; i += 256) {
            const float4* crow = (const float4*)(centres + (size_t)i * DIM);
            float s1 = 0.f, s2 = 0.f;
            #pragma unroll 8
            for (int j = 0; j < 32; j++) {
                float4 cv = crow[j];
                float4 fv = ((const float4*)fvec)[j];
                s1 += fv.x * cv.x + fv.y * cv.y + fv.z * cv.z + fv.w * cv.w;
                s2 += cv.x * cv.x + cv.y * cv.y + cv.z * cv.z + cv.w * cv.w;
            }
            float d2 = fn + s2 - 2.f * s1;
            if (d2 < edge2) {
                unsigned int p = atomicAdd(&s_kn, 1u);
                if (p < KMAX) { kd2[p] = d2; kidx[p] = i; }
            }
        }
        __syncthreads();
        kn = (int)min(s_kn, (unsigned)KMAX);
    }

    // --- exact top-KNN among kn (tie-break: smaller index, matching top_k)
    int is64 = s_is64;
    for (int t = tid; t < kn; t += 256) {
        float dt = kd2[t];
        int   it = kidx[t];
        int r = 0;
        for (int j = 0; j < kn; j++) {
            float dj = kd2[j];
            r += (dj < dt) || (dj == dt && kidx[j] < it);
        }
        if (r < KNN) {
            float w = expf(-dt * GC) * expf(wgt[it]);
            int l = lab32[is64 ? (it << 1) : it];
            atomicAdd(&bins[l], w);
        }
    }
    __syncthreads();

    float pv = 0.f;
    if (tid < NCLS) {
        pv = bins[tid];
        if (pv == 0.f) pv = 1e-10f;
    }
    float s = pv;
    #pragma unroll
    for (int o = 16; o; o >>= 1) s += __shfl_xor_sync(0xFFFFFFFFu, s, o);
    if ((tid & 31) == 0 && tid < NCLS) s_red[tid >> 5] = s;
    __syncthreads();
    if (tid == 0) s_red[0] = s_red[0] + s_red[1] + s_red[2] + s_red[3];
    __syncthreads();
    if (tid < NCLS)
        out[(size_t)b * NCLS + tid] = logf(pv / s_red[0]);
}

// ---------------- launch ----------------------------------------------------
extern "C" void kernel_launch(void* const* d_in, const int* in_sizes, int n_in,
                              void* d_out, int out_size) {
    const float* features = (const float*)d_in[0];
    const float* centres  = (const float*)d_in[1];
    const float* weight   = (const float*)d_in[2];
    const int*   labels   = (const int*)d_in[3];
    float* out = (float*)d_out;

    prep_kernel<<<NBLK_B + NBLK_A, 256>>>(features, centres);

    cudaFuncSetAttribute(sample_mma_kernel,
                         cudaFuncAttributeMaxDynamicSharedMemorySize, SMT);
    cudaFuncSetAttribute(dist_mma_kernel,
                         cudaFuncAttributeMaxDynamicSharedMemorySize, SMT);

    sample_mma_kernel<<<dim3(BATCH / 128, SKIP64), 256, SMT>>>();
    thresh_kernel<<<BATCH, 256>>>();
    dist_mma_kernel<<<dim3(BATCH / 128, NT64 - SKIP64), 256, SMT>>>();
    select_kernel<<<BATCH, 256>>>(features, centres, weight, labels, out);
}